// round 1
// baseline (speedup 1.0000x reference)
#include <cuda_runtime.h>
#include <cuda_bf16.h>
#include <cstddef>

// Problem constants
#define SEQ   2048
#define BATCH 64
#define NIN   256
#define HID   256

// Scratch: x_proj[s][b][h]  (134 MB device global — allowed scratch mechanism)
__device__ float g_xp[(size_t)SEQ * BATCH * HID];

// ---------------------------------------------------------------------------
// Kernel 1: input projection GEMM
//   g_xp[m][n] = sum_k X[m][k] * W_ih[n][k] + b_ih[n] + b_hh[n]
//   M = SEQ*BATCH = 131072, N = HID = 256, K = NIN = 256
// Tiles: BM=128, BN=64, BK=32, 256 threads, 8x4 accum per thread.
// ---------------------------------------------------------------------------
__global__ void __launch_bounds__(256) proj_kernel(
    const float* __restrict__ X,
    const float* __restrict__ W,
    const float* __restrict__ b_ih,
    const float* __restrict__ b_hh)
{
    constexpr int BM = 128, BN = 64, BK = 32;
    __shared__ float As[BK][BM + 1];   // [k][m], padded
    __shared__ float Bs[BK][BN + 1];   // [k][n], padded

    const int tid = threadIdx.x;
    const int m0  = blockIdx.x * BM;
    const int n0  = blockIdx.y * BN;
    const int tx  = tid & 15;          // 0..15 -> n
    const int ty  = tid >> 4;          // 0..15 -> m

    float acc[8][4];
#pragma unroll
    for (int i = 0; i < 8; i++)
#pragma unroll
        for (int jn = 0; jn < 4; jn++) acc[i][jn] = 0.f;

    for (int kb = 0; kb < NIN; kb += BK) {
        // Load A tile: 128x32 = 1024 float4 (4 per thread), transpose into As[k][m]
#pragma unroll
        for (int it = 0; it < 4; it++) {
            int idx = tid + it * 256;
            int r   = idx >> 3;        // 0..127 (m)
            int c4  = idx & 7;         // 0..7  (k/4)
            float4 v = *(const float4*)&X[(size_t)(m0 + r) * NIN + kb + c4 * 4];
            As[c4 * 4 + 0][r] = v.x;
            As[c4 * 4 + 1][r] = v.y;
            As[c4 * 4 + 2][r] = v.z;
            As[c4 * 4 + 3][r] = v.w;
        }
        // Load B tile: 64x32 = 512 float4 (2 per thread), transpose into Bs[k][n]
#pragma unroll
        for (int it = 0; it < 2; it++) {
            int idx = tid + it * 256;
            int r   = idx >> 3;        // 0..63 (n)
            int c4  = idx & 7;
            float4 v = *(const float4*)&W[(size_t)(n0 + r) * NIN + kb + c4 * 4];
            Bs[c4 * 4 + 0][r] = v.x;
            Bs[c4 * 4 + 1][r] = v.y;
            Bs[c4 * 4 + 2][r] = v.z;
            Bs[c4 * 4 + 3][r] = v.w;
        }
        __syncthreads();

#pragma unroll
        for (int k = 0; k < BK; k++) {
            float a[8], bb[4];
#pragma unroll
            for (int i = 0; i < 8; i++) a[i] = As[k][ty * 8 + i];
#pragma unroll
            for (int jn = 0; jn < 4; jn++) bb[jn] = Bs[k][tx * 4 + jn];
#pragma unroll
            for (int i = 0; i < 8; i++)
#pragma unroll
                for (int jn = 0; jn < 4; jn++)
                    acc[i][jn] = fmaf(a[i], bb[jn], acc[i][jn]);
        }
        __syncthreads();
    }

    // Epilogue: add (b_ih + b_hh), vectorized float4 stores
    const int nbase = n0 + tx * 4;
    float4 bias;
    bias.x = b_ih[nbase + 0] + b_hh[nbase + 0];
    bias.y = b_ih[nbase + 1] + b_hh[nbase + 1];
    bias.z = b_ih[nbase + 2] + b_hh[nbase + 2];
    bias.w = b_ih[nbase + 3] + b_hh[nbase + 3];
#pragma unroll
    for (int i = 0; i < 8; i++) {
        int m = m0 + ty * 8 + i;
        float4 v;
        v.x = acc[i][0] + bias.x;
        v.y = acc[i][1] + bias.y;
        v.z = acc[i][2] + bias.z;
        v.w = acc[i][3] + bias.w;
        *(float4*)&g_xp[(size_t)m * HID + nbase] = v;
    }
}

// ---------------------------------------------------------------------------
// Kernel 2: serial recurrence, one CTA per batch element.
//   512 threads: thread t -> output row j = t&255, k-half = t>>8 (128 k's).
//   Per thread: 64 weights in registers (k0..k0+63), 64 in SMEM (k0+64..k0+127).
//   h double-buffered in SMEM; xp prefetched one step ahead.
// ---------------------------------------------------------------------------
__global__ void __launch_bounds__(512, 1) rnn_kernel(
    const float* __restrict__ W_hh,
    float* __restrict__ out)
{
    extern __shared__ float smem[];
    float* Wsh  = smem;                         // 512 rows * 68 floats (padded)
    float* hbuf = Wsh + 512 * 68;               // 2 * 256
    float* psum = hbuf + 512;                   // 256

    const int t    = threadIdx.x;
    const int j    = t & 255;
    const int half = t >> 8;
    const int b    = blockIdx.x;
    const int k0   = half << 7;                 // 0 or 128

    // --- Load this thread's 64 register weights: W_hh[j][k0 .. k0+63]
    float w[64];
    const float* wrow = W_hh + (size_t)j * HID + k0;
#pragma unroll
    for (int i = 0; i < 16; i++) {
        float4 v = *(const float4*)(wrow + i * 4);
        w[4 * i + 0] = v.x; w[4 * i + 1] = v.y;
        w[4 * i + 2] = v.z; w[4 * i + 3] = v.w;
    }
    // --- Fill SMEM weights: W_hh[j][k0+64 .. k0+127], row stride 68 (conflict-free f4)
    float* wshrow = Wsh + t * 68;
#pragma unroll
    for (int i = 0; i < 16; i++) {
        ((float4*)wshrow)[i] = *(const float4*)(wrow + 64 + i * 4);
    }
    // h0 = 0
    if (t < 256) { hbuf[t] = 0.f; hbuf[256 + t] = 0.f; }
    __syncthreads();

    const float* xpb = g_xp + (size_t)b * HID;  // + s*BATCH*HID + j
    float xpnext = (half == 0) ? xpb[j] : 0.f;  // prefetch s=0

    for (int s = 0; s < SEQ; s++) {
        const float* hc = hbuf + ((s & 1) << 8);
        float*       hn = hbuf + (((s + 1) & 1) << 8);

        float xpcur = xpnext;
        if (half == 0 && s + 1 < SEQ)
            xpnext = xpb[(size_t)(s + 1) * BATCH * HID + j];   // hidden under compute

        // ---- 128 MACs: 64 from registers, 64 from SMEM; h broadcast LDS.128 ----
        const float4* h4  = (const float4*)(hc + k0);
        const float4* w4s = (const float4*)wshrow;
        float acc0 = 0.f, acc1 = 0.f;
#pragma unroll
        for (int i = 0; i < 16; i++) {
            float4 hv = h4[i];
            acc0 = fmaf(w[4 * i + 0], hv.x, acc0);
            acc1 = fmaf(w[4 * i + 1], hv.y, acc1);
            acc0 = fmaf(w[4 * i + 2], hv.z, acc0);
            acc1 = fmaf(w[4 * i + 3], hv.w, acc1);
        }
#pragma unroll
        for (int i = 0; i < 16; i++) {
            float4 hv = h4[16 + i];
            float4 wv = w4s[i];
            acc0 = fmaf(wv.x, hv.x, acc0);
            acc1 = fmaf(wv.y, hv.y, acc1);
            acc0 = fmaf(wv.z, hv.z, acc0);
            acc1 = fmaf(wv.w, hv.w, acc1);
        }
        float acc = acc0 + acc1;

        if (half) psum[j] = acc;
        __syncthreads();
        if (!half) {
            float v = tanhf(acc + psum[j] + xpcur);
            hn[j] = v;
            out[((size_t)s * BATCH + b) * HID + j] = v;
        }
        __syncthreads();
    }
}

// ---------------------------------------------------------------------------
extern "C" void kernel_launch(void* const* d_in, const int* in_sizes, int n_in,
                              void* d_out, int out_size)
{
    const float* input = (const float*)d_in[0];   // [SEQ, BATCH, NIN]
    const float* W_ih  = (const float*)d_in[1];   // [HID, NIN]
    const float* W_hh  = (const float*)d_in[2];   // [HID, HID]
    const float* b_ih  = (const float*)d_in[3];   // [HID]
    const float* b_hh  = (const float*)d_in[4];   // [HID]
    float* out = (float*)d_out;                   // [SEQ*BATCH, HID]

    // Recurrence kernel needs ~139 KB dynamic SMEM
    const int rnn_smem = (512 * 68 + 512 + 256) * (int)sizeof(float);
    cudaFuncSetAttribute(rnn_kernel, cudaFuncAttributeMaxDynamicSharedMemorySize,
                         rnn_smem);

    // 1) projection: grid (M/128, N/64)
    dim3 pgrid((SEQ * BATCH) / 128, HID / 64);
    proj_kernel<<<pgrid, 256>>>(input, W_ih, b_ih, b_hh);

    // 2) recurrence: one CTA per batch element
    rnn_kernel<<<BATCH, 512, rnn_smem>>>(W_hh, out);
}

// round 2
// speedup vs baseline: 1.8160x; 1.8160x over previous
#include <cuda_runtime.h>
#include <cuda_bf16.h>
#include <cstddef>
#include <cstdint>

#define SEQ   2048
#define BATCH 64
#define NIN   256
#define HID   256

// Scratch: x_proj[s][b][h]
__device__ float g_xp[(size_t)SEQ * BATCH * HID];

// ---------------------------------------------------------------------------
// helpers
// ---------------------------------------------------------------------------
__device__ __forceinline__ uint32_t smem_u32(const void* p) {
    uint32_t a;
    asm("{ .reg .u64 t; cvta.to.shared.u64 t, %1; cvt.u32.u64 %0, t; }"
        : "=r"(a) : "l"(p));
    return a;
}

// packed f32x2 fma: acc = a*b + acc  (lanewise, IEEE rn per lane)
#define FMA2(acc, a, b)                                             \
    asm("fma.rn.f32x2 %0, %1, %2, %3;"                              \
        : "=l"(acc) : "l"(a), "l"(b), "l"(acc))

__device__ __forceinline__ unsigned long long pack_dup(float x) {
    unsigned long long d;
    asm("mov.b64 %0, {%1, %1};" : "=l"(d) : "r"(__float_as_uint(x)));
    return d;
}
__device__ __forceinline__ float2 unpack2(unsigned long long v) {
    float2 r;
    asm("mov.b64 {%0, %1}, %2;" : "=f"(r.x), "=f"(r.y) : "l"(v));
    return r;
}

__device__ __forceinline__ void mbar_wait(uint32_t mbar, uint32_t parity) {
    asm volatile(
        "{\n\t"
        ".reg .pred P;\n"
        "$WL%=:\n\t"
        "mbarrier.try_wait.parity.acquire.cta.shared::cta.b64 P, [%0], %1, 0x989680;\n\t"
        "@!P bra $WL%=;\n\t"
        "}"
        :: "r"(mbar), "r"(parity) : "memory");
}

// ---------------------------------------------------------------------------
// Kernel 1: input projection GEMM (f32x2 FFMA2 inner loop)
//   g_xp[m][n] = sum_k X[m][k] * W_ih[n][k] + b_ih[n] + b_hh[n]
//   M = 131072, N = 256, K = 256.  BM=128, BN=64, BK=32, 256 threads.
//   Per thread: 8 m-rows (as 4 m-pairs) x 4 n-cols, accumulated in f32x2.
// ---------------------------------------------------------------------------
__global__ void __launch_bounds__(256) proj_kernel(
    const float* __restrict__ X,
    const float* __restrict__ W,
    const float* __restrict__ b_ih,
    const float* __restrict__ b_hh)
{
    constexpr int BM = 128, BN = 64, BK = 32;
    constexpr int APAD = 4, BPAD = 4;              // keep rows 16B-aligned
    __shared__ float As[BK][BM + APAD];            // [k][m]
    __shared__ float Bs[BK][BN + BPAD];            // [k][n]

    const int tid = threadIdx.x;
    const int m0  = blockIdx.x * BM;
    const int n0  = blockIdx.y * BN;
    const int tx  = tid & 15;          // n group
    const int ty  = tid >> 4;          // m group

    unsigned long long acc2[4][4];     // [m-pair][n]
#pragma unroll
    for (int i = 0; i < 4; i++)
#pragma unroll
        for (int j = 0; j < 4; j++) acc2[i][j] = 0ULL;

    for (int kb = 0; kb < NIN; kb += BK) {
        // A tile: 128x32, transpose into As[k][m]
#pragma unroll
        for (int it = 0; it < 4; it++) {
            int idx = tid + it * 256;
            int r   = idx >> 3;
            int c4  = idx & 7;
            float4 v = *(const float4*)&X[(size_t)(m0 + r) * NIN + kb + c4 * 4];
            As[c4 * 4 + 0][r] = v.x;
            As[c4 * 4 + 1][r] = v.y;
            As[c4 * 4 + 2][r] = v.z;
            As[c4 * 4 + 3][r] = v.w;
        }
        // B tile: 64x32, transpose into Bs[k][n]
#pragma unroll
        for (int it = 0; it < 2; it++) {
            int idx = tid + it * 256;
            int r   = idx >> 3;
            int c4  = idx & 7;
            float4 v = *(const float4*)&W[(size_t)(n0 + r) * NIN + kb + c4 * 4];
            Bs[c4 * 4 + 0][r] = v.x;
            Bs[c4 * 4 + 1][r] = v.y;
            Bs[c4 * 4 + 2][r] = v.z;
            Bs[c4 * 4 + 3][r] = v.w;
        }
        __syncthreads();

#pragma unroll
        for (int k = 0; k < BK; k++) {
            // 8 consecutive m values as 4 u64 pairs (16B-aligned)
            const ulonglong2* ap = (const ulonglong2*)&As[k][ty * 8];
            ulonglong2 av0 = ap[0];
            ulonglong2 av1 = ap[1];
            float4 bv = *(const float4*)&Bs[k][tx * 4];
            unsigned long long bd0 = pack_dup(bv.x);
            unsigned long long bd1 = pack_dup(bv.y);
            unsigned long long bd2 = pack_dup(bv.z);
            unsigned long long bd3 = pack_dup(bv.w);
            FMA2(acc2[0][0], av0.x, bd0); FMA2(acc2[0][1], av0.x, bd1);
            FMA2(acc2[0][2], av0.x, bd2); FMA2(acc2[0][3], av0.x, bd3);
            FMA2(acc2[1][0], av0.y, bd0); FMA2(acc2[1][1], av0.y, bd1);
            FMA2(acc2[1][2], av0.y, bd2); FMA2(acc2[1][3], av0.y, bd3);
            FMA2(acc2[2][0], av1.x, bd0); FMA2(acc2[2][1], av1.x, bd1);
            FMA2(acc2[2][2], av1.x, bd2); FMA2(acc2[2][3], av1.x, bd3);
            FMA2(acc2[3][0], av1.y, bd0); FMA2(acc2[3][1], av1.y, bd1);
            FMA2(acc2[3][2], av1.y, bd2); FMA2(acc2[3][3], av1.y, bd3);
        }
        __syncthreads();
    }

    // Epilogue
    const int nbase = n0 + tx * 4;
    float4 bias;
    bias.x = b_ih[nbase + 0] + b_hh[nbase + 0];
    bias.y = b_ih[nbase + 1] + b_hh[nbase + 1];
    bias.z = b_ih[nbase + 2] + b_hh[nbase + 2];
    bias.w = b_ih[nbase + 3] + b_hh[nbase + 3];
#pragma unroll
    for (int mi = 0; mi < 4; mi++) {
        float2 c0 = unpack2(acc2[mi][0]);
        float2 c1 = unpack2(acc2[mi][1]);
        float2 c2 = unpack2(acc2[mi][2]);
        float2 c3 = unpack2(acc2[mi][3]);
        int mA = m0 + ty * 8 + 2 * mi;
        float4 v0 = { c0.x + bias.x, c1.x + bias.y, c2.x + bias.z, c3.x + bias.w };
        float4 v1 = { c0.y + bias.x, c1.y + bias.y, c2.y + bias.z, c3.y + bias.w };
        *(float4*)&g_xp[(size_t)mA * HID + nbase]       = v0;
        *(float4*)&g_xp[(size_t)(mA + 1) * HID + nbase] = v1;
    }
}

// ---------------------------------------------------------------------------
// Kernel 2: serial recurrence, cluster of 2 CTAs per batch element.
//   CTA pair (2b, 2b+1): rank = k-half. 256 threads; thread t owns output
//   row t over k in [rank*128, rank*128+128). All 128 weights in registers
//   as 64 f32x2 pairs. Per step:
//     - dot over own k-half from double-buffered h in SMEM (broadcast LDS)
//     - st.async partial -> peer's pbuf[s&1][t], signals peer mbar[s&1]
//     - wait own mbar[s&1] (parity (s>>1)&1), combine, tanh, store out
//   One __syncthreads per step. Buffer-reuse safety is transitively gated
//   through the peer's data dependence (analyzed: peer rewrites pbuf[s&1]
//   at s+2 only after receiving ALL of our s+1 partials, which follow the
//   end-of-s barrier that follows every local read of pbuf[s&1]/hbuf[s&1]).
// ---------------------------------------------------------------------------
__global__ void __launch_bounds__(256, 1) __cluster_dims__(2, 1, 1)
rnn2_kernel(const float* __restrict__ W_hh, float* __restrict__ out)
{
    __shared__ float hbuf[2][256];                 // double-buffered h
    __shared__ float pbuf[2][256];                 // peer-written partials
    __shared__ __align__(8) unsigned long long mbar[2];

    const int      t    = threadIdx.x;
    const uint32_t rank = blockIdx.x & 1;
    const int      b    = blockIdx.x >> 1;
    const int      k0   = rank << 7;               // 0 or 128

    // ---- weights into registers: W_hh[t][k0 .. k0+127] as 64 u64 pairs
    unsigned long long w2[64];
    {
        const ulonglong2* wp =
            (const ulonglong2*)(W_hh + (size_t)t * HID + k0);
#pragma unroll
        for (int i = 0; i < 32; i++) {
            ulonglong2 v = wp[i];
            w2[2 * i]     = v.x;
            w2[2 * i + 1] = v.y;
        }
    }

    // ---- init
    hbuf[0][t] = 0.f;
    if (t == 0) {
        asm volatile("mbarrier.init.shared.b64 [%0], 1;"
                     :: "r"(smem_u32(&mbar[0])) : "memory");
        asm volatile("mbarrier.init.shared.b64 [%0], 1;"
                     :: "r"(smem_u32(&mbar[1])) : "memory");
    }
    __syncthreads();
    asm volatile("barrier.cluster.arrive.aligned;" ::: "memory");
    asm volatile("barrier.cluster.wait.aligned;"   ::: "memory");

    // ---- remote addresses (peer CTA in cluster)
    const uint32_t peer      = rank ^ 1u;
    const uint32_t pbuf_loc  = smem_u32(&pbuf[0][0]);
    const uint32_t mbar_loc  = smem_u32(&mbar[0]);
    uint32_t pbuf_rem, mbar_rem;
    asm("mapa.shared::cluster.u32 %0, %1, %2;"
        : "=r"(pbuf_rem) : "r"(pbuf_loc), "r"(peer));
    asm("mapa.shared::cluster.u32 %0, %1, %2;"
        : "=r"(mbar_rem) : "r"(mbar_loc), "r"(peer));

    // ---- xp prefetch window (3 deep)
    const float* xpb = g_xp + (size_t)b * HID + t;
    float xp0 = xpb[0];
    float xp1 = xpb[(size_t)1 * BATCH * HID];
    float xp2 = xpb[(size_t)2 * BATCH * HID];

    float* outp = out + (size_t)b * HID + t;

#pragma unroll 1
    for (int s = 0; s < SEQ; s++) {
        // prefetch xp[s+3] (hidden under compute + comm)
        float xpn = 0.f;
        if (s + 3 < SEQ) xpn = xpb[(size_t)(s + 3) * BATCH * HID];

        // ---- dot over own k-half: 64 FFMA2, broadcast LDS.128 h loads
        const ulonglong2* hp = (const ulonglong2*)(&hbuf[s & 1][0] + k0);
        unsigned long long a0 = 0ULL, a1 = 0ULL, a2 = 0ULL, a3 = 0ULL;
#pragma unroll
        for (int i = 0; i < 16; i++) {
            ulonglong2 h01 = hp[2 * i];
            ulonglong2 h23 = hp[2 * i + 1];
            FMA2(a0, w2[4 * i + 0], h01.x);
            FMA2(a1, w2[4 * i + 1], h01.y);
            FMA2(a2, w2[4 * i + 2], h23.x);
            FMA2(a3, w2[4 * i + 3], h23.y);
        }
        float2 f0 = unpack2(a0), f1 = unpack2(a1);
        float2 f2 = unpack2(a2), f3 = unpack2(a3);
        float mine = ((f0.x + f0.y) + (f1.x + f1.y))
                   + ((f2.x + f2.y) + (f3.x + f3.y));

        // ---- send partial to peer: pbuf[s&1][t] on the peer CTA
        const uint32_t bufsel = (uint32_t)(s & 1);
        asm volatile(
            "st.async.shared::cluster.mbarrier::complete_tx::bytes.b32 "
            "[%0], %1, [%2];"
            :: "r"(pbuf_rem + (bufsel << 10) + ((uint32_t)t << 2)),
               "r"(__float_as_uint(mine)),
               "r"(mbar_rem + bufsel * 8)
            : "memory");

        if (t == 0) {
            asm volatile(
                "mbarrier.arrive.expect_tx.shared.b64 _, [%0], 1024;"
                :: "r"(mbar_loc + bufsel * 8) : "memory");
        }
        mbar_wait(mbar_loc + bufsel * 8, (uint32_t)((s >> 1) & 1));

        // ---- combine (deterministic order: k-half0 first), tanh, store
        float theirs = pbuf[s & 1][t];
        float lo = rank ? theirs : mine;
        float hi = rank ? mine   : theirs;
        float hv = tanhf(xp0 + (lo + hi));
        if ((uint32_t)(t >> 7) == rank)            // only our half is read
            hbuf[(s + 1) & 1][t] = hv;
        if ((uint32_t)(t >> 7) == rank)            // split the global store
            outp[(size_t)s * BATCH * HID] = hv;

        xp0 = xp1; xp1 = xp2; xp2 = xpn;
        __syncthreads();                            // hbuf[(s+1)&1] ready
    }

    asm volatile("barrier.cluster.arrive.aligned;" ::: "memory");
    asm volatile("barrier.cluster.wait.aligned;"   ::: "memory");
}

// ---------------------------------------------------------------------------
extern "C" void kernel_launch(void* const* d_in, const int* in_sizes, int n_in,
                              void* d_out, int out_size)
{
    const float* input = (const float*)d_in[0];   // [SEQ, BATCH, NIN]
    const float* W_ih  = (const float*)d_in[1];   // [HID, NIN]
    const float* W_hh  = (const float*)d_in[2];   // [HID, HID]
    const float* b_ih  = (const float*)d_in[3];   // [HID]
    const float* b_hh  = (const float*)d_in[4];   // [HID]
    float* out = (float*)d_out;                   // [SEQ*BATCH, HID]

    // 1) projection
    dim3 pgrid((SEQ * BATCH) / 128, HID / 64);
    proj_kernel<<<pgrid, 256>>>(input, W_ih, b_ih, b_hh);

    // 2) recurrence: 2 CTAs (one cluster) per batch element
    rnn2_kernel<<<BATCH * 2, 256>>>(W_hh, out);
}